// round 15
// baseline (speedup 1.0000x reference)
#include <cuda_runtime.h>
#include <cuda_bf16.h>
#include <cstdint>

// R15 = R14 + conv0 interleaved-uint2 A (LDS.64) + conv3 chunked weights (3 CTAs/SM).

#define BL 3072

__device__ float g_s0[BL * 32 * 21 * 21];
__device__ float g_s1[BL * 32 * 9 * 9];
__device__ float g_s2[BL * 64 * 4 * 4];
__device__ float g_s3[BL * 256];
__device__ uint4 g_w0B[7 * 32 * 4];
__device__ uint4 g_w1B[25 * 2 * 32 * 4];
__device__ uint4 g_w2B[16 * 2 * 32 * 8];

__device__ __forceinline__ float prelu(float v, float a) {
    return v >= 0.0f ? v : a * v;
}
__device__ __forceinline__ uint32_t bf16pack(float vlo, float vhi) {
    uint32_t r;
    asm("cvt.rn.bf16x2.f32 %0, %1, %2;" : "=r"(r) : "f"(vhi), "f"(vlo));
    return r;
}
__device__ __forceinline__ void mma_bf16(float4& d,
    uint32_t a0, uint32_t a1, uint32_t a2, uint32_t a3, uint32_t b0, uint32_t b1) {
    asm volatile(
        "mma.sync.aligned.m16n8k16.row.col.f32.bf16.bf16.f32 "
        "{%0,%1,%2,%3}, {%4,%5,%6,%7}, {%8,%9}, {%0,%1,%2,%3};"
        : "+f"(d.x), "+f"(d.y), "+f"(d.z), "+f"(d.w)
        : "r"(a0), "r"(a1), "r"(a2), "r"(a3), "r"(b0), "r"(b1));
}
__device__ __forceinline__ void split2(float v0, float v1, uint32_t& hp, uint32_t& lp) {
    hp = bf16pack(v0, v1);
    float r0 = __uint_as_float(hp << 16);
    float r1 = __uint_as_float(hp & 0xffff0000u);
    lp = bf16pack(v0 - r0, v1 - r1);
}

__global__ void k_w0prep(const float* __restrict__ w0) {
    const int c = blockIdx.x, lane = threadIdx.x & 31, nf = threadIdx.x >> 5;
    const int n = nf * 8 + (lane >> 2), cb = lane & 3, icp = cb & 1;
    const int p0 = 4 * c + (cb >> 1), p2 = p0 + 2;
    float v0 = 0.f, v1 = 0.f, v2 = 0.f, v3 = 0.f;
    if (p0 < 25) { v0 = w0[n * 100 + (2 * icp) * 25 + p0]; v1 = w0[n * 100 + (2 * icp + 1) * 25 + p0]; }
    if (p2 < 25) { v2 = w0[n * 100 + (2 * icp) * 25 + p2]; v3 = w0[n * 100 + (2 * icp + 1) * 25 + p2]; }
    uint32_t hb0, lb0, hb1, lb1;
    split2(v0, v1, hb0, lb0);
    split2(v2, v3, hb1, lb1);
    g_w0B[(c * 32 + lane) * 4 + nf] = make_uint4(hb0, hb1, lb0, lb1);
}
__global__ void k_w1prep(const float* __restrict__ w1) {
    const int p = blockIdx.x, g = blockIdx.y, lane = threadIdx.x & 31, nf = threadIdx.x >> 5;
    const int n = nf * 8 + (lane >> 2), ic0 = g * 16 + 2 * (lane & 3);
    float v0 = w1[n * 800 + ic0 * 25 + p];
    float v1 = w1[n * 800 + (ic0 + 1) * 25 + p];
    float v8 = w1[n * 800 + (ic0 + 8) * 25 + p];
    float v9 = w1[n * 800 + (ic0 + 9) * 25 + p];
    uint32_t hb0, lb0, hb1, lb1;
    split2(v0, v1, hb0, lb0);
    split2(v8, v9, hb1, lb1);
    g_w1B[((p * 2 + g) * 32 + lane) * 4 + nf] = make_uint4(hb0, hb1, lb0, lb1);
}
__global__ void k_w2prep(const float* __restrict__ w2) {
    const int p = blockIdx.x, g = blockIdx.y, lane = threadIdx.x & 31, nf = threadIdx.x >> 5;
    const int n = nf * 8 + (lane >> 2), ic0 = g * 16 + 2 * (lane & 3);
    float v0 = w2[n * 512 + ic0 * 16 + p];
    float v1 = w2[n * 512 + (ic0 + 1) * 16 + p];
    float v8 = w2[n * 512 + (ic0 + 8) * 16 + p];
    float v9 = w2[n * 512 + (ic0 + 9) * 16 + p];
    uint32_t hb0, lb0, hb1, lb1;
    split2(v0, v1, hb0, lb0);
    split2(v8, v9, hb1, lb1);
    g_w2B[((p * 2 + g) * 32 + lane) * 8 + nf] = make_uint4(hb0, hb1, lb0, lb1);
}

// conv0: grid=BL, block=224, tile-quads, interleaved uint2 image (LDS.64).
#define C0_PIX  54
#define C0_U2   (47 * C0_PIX * 2)       // 5076 uint2
#define SMEM_C0 (C0_U2 * 8)

__global__ void __launch_bounds__(224, 2)
k_conv0_mma(const float* __restrict__ x,
            const float* __restrict__ b, const float* __restrict__ ap) {
    extern __shared__ uint2 sI0[];
    const int tid = threadIdx.x, wid = tid >> 5, lid = tid & 31, bl = blockIdx.x;

    for (int i = tid; i < C0_U2; i += 224) sI0[i] = make_uint2(0u, 0u);
    __syncthreads();
    const float* xb = x + bl * 8100;
    for (int i = tid; i < 4050; i += 224) {
        int pix = i >> 1, pr = i & 1;
        int y = pix / 45, xx = pix - y * 45;
        float v0 = xb[(2 * pr) * 2025 + pix];
        float v1 = xb[(2 * pr + 1) * 2025 + pix];
        uint32_t hp, lp;
        split2(v0, v1, hp, lp);
        sI0[((y + 1) * C0_PIX + (xx + 1)) * 2 + pr] = make_uint2(hp, lp);
    }
    __syncthreads();

    const int cb = lid & 3, icp = cb & 1;
    int off0[7], off2[7];
#pragma unroll
    for (int c = 0; c < 7; ++c) {
        int p0 = 4 * c + (cb >> 1), p2 = p0 + 2;
        if (p0 > 24) p0 = 24;
        if (p2 > 24) p2 = 24;
        off0[c] = ((p0 / 5) * C0_PIX + (p0 % 5)) * 2 + icp;
        off2[c] = ((p2 / 5) * C0_PIX + (p2 % 5)) * 2 + icp;
    }
    float bx[4], by[4];
#pragma unroll
    for (int nf = 0; nf < 4; ++nf) {
        bx[nf] = b[nf * 8 + 2 * cb];
        by[nf] = b[nf * 8 + 2 * cb + 1];
    }
    const float a = *ap;
    float* out = g_s0 + bl * 14112;
    const bool wr = ((lid >> 2) & 3) == 0;
    const int qoff = (lid >= 16) ? 1 : 0;

    for (int tq = 0; tq < 4; ++tq) {
        int rb[4][2];
#pragma unroll
        for (int u = 0; u < 4; ++u) {
            const int tt = wid * 16 + tq * 4 + u;
#pragma unroll
            for (int j = 0; j < 2; ++j) {
                int m = tt * 16 + (lid >> 2) + j * 8;
                if (m >= 1764) m = 0;
                int q = m >> 2, s = m & 3;
                int yy = 2 * (q / 21) + (s >> 1);
                int xx = 2 * (q % 21) + (s & 1);
                rb[u][j] = (yy * C0_PIX + xx) * 2;
            }
        }
        float4 acc[4][4];
#pragma unroll
        for (int u = 0; u < 4; ++u)
#pragma unroll
            for (int nf = 0; nf < 4; ++nf) acc[u][nf] = make_float4(0.f, 0.f, 0.f, 0.f);

#pragma unroll
        for (int c = 0; c < 7; ++c) {
            const uint4* gB = g_w0B + (c * 32 + lid) * 4;
            uint4 B0 = gB[0], B1 = gB[1], B2 = gB[2], B3 = gB[3];
#pragma unroll
            for (int u = 0; u < 4; ++u) {
                uint2 A0 = sI0[rb[u][0] + off0[c]];
                uint2 A1 = sI0[rb[u][1] + off0[c]];
                uint2 A2 = sI0[rb[u][0] + off2[c]];
                uint2 A3 = sI0[rb[u][1] + off2[c]];
                mma_bf16(acc[u][0], A0.x, A1.x, A2.x, A3.x, B0.x, B0.y);
                mma_bf16(acc[u][1], A0.x, A1.x, A2.x, A3.x, B1.x, B1.y);
                mma_bf16(acc[u][2], A0.x, A1.x, A2.x, A3.x, B2.x, B2.y);
                mma_bf16(acc[u][3], A0.x, A1.x, A2.x, A3.x, B3.x, B3.y);
                mma_bf16(acc[u][0], A0.y, A1.y, A2.y, A3.y, B0.x, B0.y);
                mma_bf16(acc[u][1], A0.y, A1.y, A2.y, A3.y, B1.x, B1.y);
                mma_bf16(acc[u][2], A0.y, A1.y, A2.y, A3.y, B2.x, B2.y);
                mma_bf16(acc[u][3], A0.y, A1.y, A2.y, A3.y, B3.x, B3.y);
                mma_bf16(acc[u][0], A0.x, A1.x, A2.x, A3.x, B0.z, B0.w);
                mma_bf16(acc[u][1], A0.x, A1.x, A2.x, A3.x, B1.z, B1.w);
                mma_bf16(acc[u][2], A0.x, A1.x, A2.x, A3.x, B2.z, B2.w);
                mma_bf16(acc[u][3], A0.x, A1.x, A2.x, A3.x, B3.z, B3.w);
            }
        }
#pragma unroll
        for (int u = 0; u < 4; ++u) {
            const int tt = wid * 16 + tq * 4 + u;
            const int qA = tt * 4 + qoff;
            const int qB = qA + 2;
#pragma unroll
            for (int nf = 0; nf < 4; ++nf) {
                float vx = prelu(acc[u][nf].x + bx[nf], a);
                float vy = prelu(acc[u][nf].y + by[nf], a);
                float vz = prelu(acc[u][nf].z + bx[nf], a);
                float vw = prelu(acc[u][nf].w + by[nf], a);
                vx = fmaxf(vx, __shfl_xor_sync(0xffffffffu, vx, 4));
                vx = fmaxf(vx, __shfl_xor_sync(0xffffffffu, vx, 8));
                vy = fmaxf(vy, __shfl_xor_sync(0xffffffffu, vy, 4));
                vy = fmaxf(vy, __shfl_xor_sync(0xffffffffu, vy, 8));
                vz = fmaxf(vz, __shfl_xor_sync(0xffffffffu, vz, 4));
                vz = fmaxf(vz, __shfl_xor_sync(0xffffffffu, vz, 8));
                vw = fmaxf(vw, __shfl_xor_sync(0xffffffffu, vw, 4));
                vw = fmaxf(vw, __shfl_xor_sync(0xffffffffu, vw, 8));
                if (wr) {
                    int oc0 = nf * 8 + 2 * cb;
                    if (qA < 441) {
                        out[oc0 * 441 + qA]       = vx;
                        out[(oc0 + 1) * 441 + qA] = vy;
                    }
                    if (qB < 441) {
                        out[oc0 * 441 + qB]       = vz;
                        out[(oc0 + 1) * 441 + qB] = vw;
                    }
                }
            }
        }
    }
}

// conv1 (R14, unchanged): interleaved uint2, stride 20.
#define C1_STR  20
#define C1_U2   (484 * C1_STR)
#define SMEM_C1 (C1_U2 * 8)

__global__ void __launch_bounds__(224, 2)
k_conv1_mma(const float* __restrict__ b, const float* __restrict__ ap) {
    extern __shared__ uint2 sI1[];
    const int tid = threadIdx.x, wid = tid >> 5, lid = tid & 31, bl = blockIdx.x;

    for (int i = tid; i < C1_U2; i += 224) sI1[i] = make_uint2(0u, 0u);
    __syncthreads();
    const float* src = g_s0 + bl * 14112;
    for (int i = tid; i < 7056; i += 224) {
        int pr = i / 441, pix = i - pr * 441;
        int y = pix / 21, x = pix - y * 21;
        float v0 = src[(2 * pr) * 441 + pix];
        float v1 = src[(2 * pr + 1) * 441 + pix];
        uint32_t hp, lp;
        split2(v0, v1, hp, lp);
        sI1[((y + 1) * 22 + (x + 1)) * C1_STR + pr] = make_uint2(hp, lp);
    }
    __syncthreads();

    int base[3][2];
#pragma unroll
    for (int t = 0; t < 3; ++t)
#pragma unroll
        for (int j = 0; j < 2; ++j) {
            int m = (wid * 3 + t) * 16 + (lid >> 2) + j * 8;
            int mm = m < 324 ? m : 0;
            int ym = mm / 18, xm = mm - ym * 18;
            base[t][j] = (ym * 22 + xm) * C1_STR;
        }

    float4 acc[3][4];
#pragma unroll
    for (int t = 0; t < 3; ++t)
#pragma unroll
        for (int nf = 0; nf < 4; ++nf) acc[t][nf] = make_float4(0.f, 0.f, 0.f, 0.f);

    const int cb = lid & 3;
    for (int p = 0; p < 25; ++p) {
        const int ky = p / 5, kx = p - ky * 5;
        const int off = (ky * 22 + kx) * C1_STR;
#pragma unroll
        for (int g = 0; g < 2; ++g) {
            const uint4* gB = g_w1B + ((p * 2 + g) * 32 + lid) * 4;
            uint4 B0 = gB[0], B1 = gB[1], B2 = gB[2], B3 = gB[3];
            const int c = g * 8 + cb;
#pragma unroll
            for (int t = 0; t < 3; ++t) {
                const int i0 = base[t][0] + off + c;
                const int i1 = base[t][1] + off + c;
                uint2 A0 = sI1[i0];
                uint2 A1 = sI1[i1];
                uint2 A2 = sI1[i0 + 4];
                uint2 A3 = sI1[i1 + 4];
                mma_bf16(acc[t][0], A0.x, A1.x, A2.x, A3.x, B0.x, B0.y);
                mma_bf16(acc[t][1], A0.x, A1.x, A2.x, A3.x, B1.x, B1.y);
                mma_bf16(acc[t][2], A0.x, A1.x, A2.x, A3.x, B2.x, B2.y);
                mma_bf16(acc[t][3], A0.x, A1.x, A2.x, A3.x, B3.x, B3.y);
                mma_bf16(acc[t][0], A0.y, A1.y, A2.y, A3.y, B0.x, B0.y);
                mma_bf16(acc[t][1], A0.y, A1.y, A2.y, A3.y, B1.x, B1.y);
                mma_bf16(acc[t][2], A0.y, A1.y, A2.y, A3.y, B2.x, B2.y);
                mma_bf16(acc[t][3], A0.y, A1.y, A2.y, A3.y, B3.x, B3.y);
                mma_bf16(acc[t][0], A0.x, A1.x, A2.x, A3.x, B0.z, B0.w);
                mma_bf16(acc[t][1], A0.x, A1.x, A2.x, A3.x, B1.z, B1.w);
                mma_bf16(acc[t][2], A0.x, A1.x, A2.x, A3.x, B2.z, B2.w);
                mma_bf16(acc[t][3], A0.x, A1.x, A2.x, A3.x, B3.z, B3.w);
            }
        }
    }
    __syncthreads();

    const float a = *ap;
    float* stage = (float*)sI1;
    {
        const int r0 = (wid * 3) * 16 + (lid >> 2);
        const int oc0 = 2 * (lid & 3);
#pragma unroll
        for (int t = 0; t < 3; ++t) {
            int ra = r0 + t * 16, rb2 = ra + 8;
#pragma unroll
            for (int nf = 0; nf < 4; ++nf) {
                int ca = nf * 8 + oc0;
                float ba = b[ca], bb = b[ca + 1];
                stage[ra * 33 + ca]      = prelu(acc[t][nf].x + ba, a);
                stage[ra * 33 + ca + 1]  = prelu(acc[t][nf].y + bb, a);
                stage[rb2 * 33 + ca]     = prelu(acc[t][nf].z + ba, a);
                stage[rb2 * 33 + ca + 1] = prelu(acc[t][nf].w + bb, a);
            }
        }
    }
    __syncthreads();

    float* outp = g_s1 + bl * 2592;
    for (int i = tid; i < 2592; i += 224) {
        int oc = i / 81, pp = i - oc * 81;
        int py = pp / 9, px = pp - py * 9;
        int m00 = (2 * py) * 18 + 2 * px;
        float v = fmaxf(fmaxf(stage[m00 * 33 + oc],        stage[(m00 + 1) * 33 + oc]),
                        fmaxf(stage[(m00 + 18) * 33 + oc], stage[(m00 + 19) * 33 + oc]));
        outp[i] = v;
    }
}

// conv2 (R14, unchanged)
#define C2_STR  20
#define C2_IMGU (121 * C2_STR)
#define SMEM_C2 (2 * C2_IMGU * 8)

__global__ void __launch_bounds__(256, 2)
k_conv2_mma(const float* __restrict__ b, const float* __restrict__ ap) {
    extern __shared__ uint2 sI2[];
    const int tid = threadIdx.x, wid = tid >> 5, lid = tid & 31, bl = blockIdx.x;

    for (int i = tid; i < 2 * C2_IMGU; i += 256) sI2[i] = make_uint2(0u, 0u);
    __syncthreads();
    const float* src = g_s1 + bl * 2 * 2592;
    for (int i = tid; i < 2592; i += 256) {
        int img = i / 1296, rr = i - img * 1296;
        int pr = rr / 81, pix = rr - pr * 81;
        int y = pix / 9, x = pix - y * 9;
        float v0 = src[img * 2592 + (2 * pr) * 81 + pix];
        float v1 = src[img * 2592 + (2 * pr + 1) * 81 + pix];
        uint32_t hp, lp;
        split2(v0, v1, hp, lp);
        sI2[img * C2_IMGU + ((y + 1) * 11 + (x + 1)) * C2_STR + pr] = make_uint2(hp, lp);
    }
    __syncthreads();

    const int img = wid >> 2;
    int base[2];
#pragma unroll
    for (int j = 0; j < 2; ++j) {
        int m = wid * 16 + (lid >> 2) + j * 8;
        int pix = m & 63;
        int oy = pix >> 3, ox = pix & 7;
        base[j] = img * C2_IMGU + (oy * 11 + ox) * C2_STR;
    }

    float4 acc[8];
#pragma unroll
    for (int nf = 0; nf < 8; ++nf) acc[nf] = make_float4(0.f, 0.f, 0.f, 0.f);

    const int cb = lid & 3;
    for (int p = 0; p < 16; ++p) {
        const int off = ((p >> 2) * 11 + (p & 3)) * C2_STR;
#pragma unroll
        for (int g = 0; g < 2; ++g) {
            const uint4* gB = g_w2B + ((p * 2 + g) * 32 + lid) * 8;
            const int c = g * 8 + cb;
            const int i0 = base[0] + off + c;
            const int i1 = base[1] + off + c;
            uint2 A0 = sI2[i0];
            uint2 A1 = sI2[i1];
            uint2 A2 = sI2[i0 + 4];
            uint2 A3 = sI2[i1 + 4];
#pragma unroll
            for (int nf = 0; nf < 8; ++nf) {
                uint4 Bv = gB[nf];
                mma_bf16(acc[nf], A0.x, A1.x, A2.x, A3.x, Bv.x, Bv.y);
                mma_bf16(acc[nf], A0.y, A1.y, A2.y, A3.y, Bv.x, Bv.y);
                mma_bf16(acc[nf], A0.x, A1.x, A2.x, A3.x, Bv.z, Bv.w);
            }
        }
    }
    __syncthreads();

    const float a = *ap;
    float* stage = (float*)sI2;
    {
        const int r0 = wid * 16 + (lid >> 2);
        const int oc0 = 2 * (lid & 3);
#pragma unroll
        for (int nf = 0; nf < 8; ++nf) {
            int ca = nf * 8 + oc0;
            float ba = b[ca], bb = b[ca + 1];
            stage[r0 * 65 + ca]           = prelu(acc[nf].x + ba, a);
            stage[r0 * 65 + ca + 1]       = prelu(acc[nf].y + bb, a);
            stage[(r0 + 8) * 65 + ca]     = prelu(acc[nf].z + ba, a);
            stage[(r0 + 8) * 65 + ca + 1] = prelu(acc[nf].w + bb, a);
        }
    }
    __syncthreads();

    for (int i = tid; i < 2048; i += 256) {
        int im = i >> 10, rem = i & 1023;
        int oc = rem >> 4, pp = rem & 15;
        int py = pp >> 2, px = pp & 3;
        int m00 = im * 64 + (2 * py) * 8 + 2 * px;
        float v = fmaxf(fmaxf(stage[m00 * 65 + oc],       stage[(m00 + 1) * 65 + oc]),
                        fmaxf(stage[(m00 + 8) * 65 + oc], stage[(m00 + 9) * 65 + oc]));
        g_s2[((bl * 2 + im) * 64 + oc) * 16 + py * 4 + px] = v;
    }
}

// conv3: chunked weight SMEM (4 chunks of 16 ic) -> 69KB live -> 3 CTAs/SM.
#define C3_WCH (64 * 145)               // 9280 floats per chunk (stride 145)
#define SMEM_C3 ((C3_WCH + 8192) * 4)   // 69,888 B

__global__ void __launch_bounds__(256, 3)
k_conv3(const float* __restrict__ w,
        const float* __restrict__ b,
        const float* __restrict__ ap) {
    extern __shared__ float sm3[];
    float* sW  = sm3;                   // chunk: [oc][16 ic x 9 + pad]
    float* sIn = sm3 + C3_WCH;          // 8 img x 1024
    const int tid = threadIdx.x;
    const int bl0 = blockIdx.x * 8;

    const float* src = g_s2 + bl0 * 1024;
    for (int i = tid; i < 8192; i += 256) sIn[i] = src[i];

    const int oc = tid >> 2, pos = tid & 3;
    const int yy = pos >> 1, xx = pos & 1;
    const float bias = b[oc];
    const float a = *ap;

    float acc[8];
#pragma unroll
    for (int i = 0; i < 8; ++i) acc[i] = bias;

    for (int ch = 0; ch < 4; ++ch) {
        __syncthreads();
        for (int k = tid; k < 64 * 144; k += 256) {
            int o = k / 144, r = k - o * 144;
            sW[o * 145 + r] = w[o * 576 + ch * 144 + r];
        }
        __syncthreads();
#pragma unroll
        for (int icl = 0; icl < 16; ++icl) {
            const int ic = ch * 16 + icl;
            const float* wv = sW + oc * 145 + icl * 9;
            float wr[9];
#pragma unroll
            for (int j = 0; j < 9; ++j) wr[j] = wv[j];
#pragma unroll
            for (int img = 0; img < 8; ++img) {
                const float* ip = sIn + img * 1024 + ic * 16;
#pragma unroll
                for (int ky = 0; ky < 3; ++ky)
#pragma unroll
                    for (int kx = 0; kx < 3; ++kx)
                        acc[img] = fmaf(ip[(yy + ky) * 4 + (xx + kx)], wr[ky * 3 + kx], acc[img]);
            }
        }
    }
#pragma unroll
    for (int img = 0; img < 8; ++img)
        g_s3[(bl0 + img) * 256 + oc * 4 + pos] = prelu(acc[img], a);
}

// FC heads (R14 per-image version)
__global__ void k_fc(const float* __restrict__ fc1_w, const float* __restrict__ fc1_b,
                     const float* __restrict__ a4,
                     const float* __restrict__ fc2_w, const float* __restrict__ fc2_b,
                     const float* __restrict__ a5,
                     const float* __restrict__ fc3_w, const float* __restrict__ fc3_b,
                     float* __restrict__ out) {
    __shared__ float feat[256];
    __shared__ float h1[128];
    __shared__ float h2[64];
    const int bl = blockIdx.x, l = bl % 6, tid = threadIdx.x;

    feat[tid]       = g_s3[bl * 256 + tid];
    feat[tid + 128] = g_s3[bl * 256 + 128 + tid];
    __syncthreads();
    {
        float acc = fc1_b[l * 128 + tid];
        const float* W = fc1_w + l * 256 * 128 + tid;
#pragma unroll 8
        for (int i = 0; i < 256; ++i) acc = fmaf(feat[i], W[i * 128], acc);
        h1[tid] = prelu(acc, a4[l]);
    }
    __syncthreads();
    if (tid < 64) {
        float acc = fc2_b[l * 64 + tid];
        const float* W = fc2_w + l * 128 * 64 + tid;
#pragma unroll 8
        for (int i = 0; i < 128; ++i) acc = fmaf(h1[i], W[i * 64], acc);
        h2[tid] = prelu(acc, a5[l]);
    }
    __syncthreads();
    if (tid < 4) {
        float acc = fc3_b[l * 4 + tid];
        const float* W = fc3_w + l * 64 * 4 + tid;
#pragma unroll
        for (int i = 0; i < 64; ++i) acc = fmaf(h2[i], W[i * 4], acc);
        out[bl * 4 + tid] = acc;
    }
}

extern "C" void kernel_launch(void* const* d_in, const int* in_sizes, int n_in,
                              void* d_out, int out_size) {
    const float* x     = (const float*)d_in[0];
    const float* w0    = (const float*)d_in[1];
    const float* b0    = (const float*)d_in[2];
    const float* w1    = (const float*)d_in[3];
    const float* b1    = (const float*)d_in[4];
    const float* w2    = (const float*)d_in[5];
    const float* b2    = (const float*)d_in[6];
    const float* w3    = (const float*)d_in[7];
    const float* b3    = (const float*)d_in[8];
    const float* a0    = (const float*)d_in[9];
    const float* a1    = (const float*)d_in[10];
    const float* a2    = (const float*)d_in[11];
    const float* a3    = (const float*)d_in[12];
    const float* fc1_w = (const float*)d_in[13];
    const float* fc1_b = (const float*)d_in[14];
    const float* a4    = (const float*)d_in[15];
    const float* fc2_w = (const float*)d_in[16];
    const float* fc2_b = (const float*)d_in[17];
    const float* a5    = (const float*)d_in[18];
    const float* fc3_w = (const float*)d_in[19];
    const float* fc3_b = (const float*)d_in[20];
    float* out = (float*)d_out;

    cudaFuncSetAttribute(k_conv0_mma, cudaFuncAttributeMaxDynamicSharedMemorySize, SMEM_C0);
    cudaFuncSetAttribute(k_conv1_mma, cudaFuncAttributeMaxDynamicSharedMemorySize, SMEM_C1);
    cudaFuncSetAttribute(k_conv2_mma, cudaFuncAttributeMaxDynamicSharedMemorySize, SMEM_C2);
    cudaFuncSetAttribute(k_conv3, cudaFuncAttributeMaxDynamicSharedMemorySize, SMEM_C3);

    k_w0prep<<<7, 128>>>(w0);
    k_w1prep<<<dim3(25, 2), 128>>>(w1);
    k_w2prep<<<dim3(16, 2), 256>>>(w2);
    k_conv0_mma<<<BL, 224, SMEM_C0>>>(x, b0, a0);
    k_conv1_mma<<<BL, 224, SMEM_C1>>>(b1, a1);
    k_conv2_mma<<<BL / 2, 256, SMEM_C2>>>(b2, a2);
    k_conv3<<<BL / 8, 256, SMEM_C3>>>(w3, b3, a3);
    k_fc<<<BL, 128>>>(fc1_w, fc1_b, a4, fc2_w, fc2_b, a5, fc3_w, fc3_b, out);
}

// round 16
// speedup vs baseline: 1.0616x; 1.0616x over previous
#include <cuda_runtime.h>
#include <cuda_bf16.h>
#include <cstdint>

// R16 = best-of: conv0 (R12 planes) + conv1/2 (R14 interleaved) + conv3 (R15 chunked).

#define BL 3072

__device__ float g_s0[BL * 32 * 21 * 21];
__device__ float g_s1[BL * 32 * 9 * 9];
__device__ float g_s2[BL * 64 * 4 * 4];
__device__ float g_s3[BL * 256];
__device__ uint4 g_w0B[7 * 32 * 4];
__device__ uint4 g_w1B[25 * 2 * 32 * 4];
__device__ uint4 g_w2B[16 * 2 * 32 * 8];

__device__ __forceinline__ float prelu(float v, float a) {
    return v >= 0.0f ? v : a * v;
}
__device__ __forceinline__ uint32_t bf16pack(float vlo, float vhi) {
    uint32_t r;
    asm("cvt.rn.bf16x2.f32 %0, %1, %2;" : "=r"(r) : "f"(vhi), "f"(vlo));
    return r;
}
__device__ __forceinline__ void mma_bf16(float4& d,
    uint32_t a0, uint32_t a1, uint32_t a2, uint32_t a3, uint32_t b0, uint32_t b1) {
    asm volatile(
        "mma.sync.aligned.m16n8k16.row.col.f32.bf16.bf16.f32 "
        "{%0,%1,%2,%3}, {%4,%5,%6,%7}, {%8,%9}, {%0,%1,%2,%3};"
        : "+f"(d.x), "+f"(d.y), "+f"(d.z), "+f"(d.w)
        : "r"(a0), "r"(a1), "r"(a2), "r"(a3), "r"(b0), "r"(b1));
}
__device__ __forceinline__ void split2(float v0, float v1, uint32_t& hp, uint32_t& lp) {
    hp = bf16pack(v0, v1);
    float r0 = __uint_as_float(hp << 16);
    float r1 = __uint_as_float(hp & 0xffff0000u);
    lp = bf16pack(v0 - r0, v1 - r1);
}

__global__ void k_w0prep(const float* __restrict__ w0) {
    const int c = blockIdx.x, lane = threadIdx.x & 31, nf = threadIdx.x >> 5;
    const int n = nf * 8 + (lane >> 2), cb = lane & 3, icp = cb & 1;
    const int p0 = 4 * c + (cb >> 1), p2 = p0 + 2;
    float v0 = 0.f, v1 = 0.f, v2 = 0.f, v3 = 0.f;
    if (p0 < 25) { v0 = w0[n * 100 + (2 * icp) * 25 + p0]; v1 = w0[n * 100 + (2 * icp + 1) * 25 + p0]; }
    if (p2 < 25) { v2 = w0[n * 100 + (2 * icp) * 25 + p2]; v3 = w0[n * 100 + (2 * icp + 1) * 25 + p2]; }
    uint32_t hb0, lb0, hb1, lb1;
    split2(v0, v1, hb0, lb0);
    split2(v2, v3, hb1, lb1);
    g_w0B[(c * 32 + lane) * 4 + nf] = make_uint4(hb0, hb1, lb0, lb1);
}
__global__ void k_w1prep(const float* __restrict__ w1) {
    const int p = blockIdx.x, g = blockIdx.y, lane = threadIdx.x & 31, nf = threadIdx.x >> 5;
    const int n = nf * 8 + (lane >> 2), ic0 = g * 16 + 2 * (lane & 3);
    float v0 = w1[n * 800 + ic0 * 25 + p];
    float v1 = w1[n * 800 + (ic0 + 1) * 25 + p];
    float v8 = w1[n * 800 + (ic0 + 8) * 25 + p];
    float v9 = w1[n * 800 + (ic0 + 9) * 25 + p];
    uint32_t hb0, lb0, hb1, lb1;
    split2(v0, v1, hb0, lb0);
    split2(v8, v9, hb1, lb1);
    g_w1B[((p * 2 + g) * 32 + lane) * 4 + nf] = make_uint4(hb0, hb1, lb0, lb1);
}
__global__ void k_w2prep(const float* __restrict__ w2) {
    const int p = blockIdx.x, g = blockIdx.y, lane = threadIdx.x & 31, nf = threadIdx.x >> 5;
    const int n = nf * 8 + (lane >> 2), ic0 = g * 16 + 2 * (lane & 3);
    float v0 = w2[n * 512 + ic0 * 16 + p];
    float v1 = w2[n * 512 + (ic0 + 1) * 16 + p];
    float v8 = w2[n * 512 + (ic0 + 8) * 16 + p];
    float v9 = w2[n * 512 + (ic0 + 9) * 16 + p];
    uint32_t hb0, lb0, hb1, lb1;
    split2(v0, v1, hb0, lb0);
    split2(v8, v9, hb1, lb1);
    g_w2B[((p * 2 + g) * 32 + lane) * 8 + nf] = make_uint4(hb0, hb1, lb0, lb1);
}

// conv0 (R12 separate hi/lo planes): grid=BL, block=224, tile-quads.
#define C0_PIX  54
#define C0_HALF (47 * C0_PIX * 2)
#define SMEM_C0 (2 * C0_HALF * 4)

__global__ void __launch_bounds__(224, 2)
k_conv0_mma(const float* __restrict__ x,
            const float* __restrict__ b, const float* __restrict__ ap) {
    extern __shared__ uint32_t sm0[];
    uint32_t* sHi = sm0;
    uint32_t* sLo = sm0 + C0_HALF;
    const int tid = threadIdx.x, wid = tid >> 5, lid = tid & 31, bl = blockIdx.x;

    for (int i = tid; i < 2 * C0_HALF; i += 224) sm0[i] = 0u;
    __syncthreads();
    const float* xb = x + bl * 8100;
    for (int i = tid; i < 4050; i += 224) {
        int pix = i >> 1, pr = i & 1;
        int y = pix / 45, xx = pix - y * 45;
        float v0 = xb[(2 * pr) * 2025 + pix];
        float v1 = xb[(2 * pr + 1) * 2025 + pix];
        uint32_t hp, lp;
        split2(v0, v1, hp, lp);
        int idx = ((y + 1) * C0_PIX + (xx + 1)) * 2 + pr;
        sHi[idx] = hp;
        sLo[idx] = lp;
    }
    __syncthreads();

    const int cb = lid & 3, icp = cb & 1;
    int off0[7], off2[7];
#pragma unroll
    for (int c = 0; c < 7; ++c) {
        int p0 = 4 * c + (cb >> 1), p2 = p0 + 2;
        if (p0 > 24) p0 = 24;
        if (p2 > 24) p2 = 24;
        off0[c] = ((p0 / 5) * C0_PIX + (p0 % 5)) * 2 + icp;
        off2[c] = ((p2 / 5) * C0_PIX + (p2 % 5)) * 2 + icp;
    }
    float bx[4], by[4];
#pragma unroll
    for (int nf = 0; nf < 4; ++nf) {
        bx[nf] = b[nf * 8 + 2 * cb];
        by[nf] = b[nf * 8 + 2 * cb + 1];
    }
    const float a = *ap;
    float* out = g_s0 + bl * 14112;
    const bool wr = ((lid >> 2) & 3) == 0;
    const int qoff = (lid >= 16) ? 1 : 0;

    for (int tq = 0; tq < 4; ++tq) {
        int rb[4][2];
#pragma unroll
        for (int u = 0; u < 4; ++u) {
            const int tt = wid * 16 + tq * 4 + u;
#pragma unroll
            for (int j = 0; j < 2; ++j) {
                int m = tt * 16 + (lid >> 2) + j * 8;
                if (m >= 1764) m = 0;
                int q = m >> 2, s = m & 3;
                int yy = 2 * (q / 21) + (s >> 1);
                int xx = 2 * (q % 21) + (s & 1);
                rb[u][j] = (yy * C0_PIX + xx) * 2;
            }
        }
        float4 acc[4][4];
#pragma unroll
        for (int u = 0; u < 4; ++u)
#pragma unroll
            for (int nf = 0; nf < 4; ++nf) acc[u][nf] = make_float4(0.f, 0.f, 0.f, 0.f);

#pragma unroll
        for (int c = 0; c < 7; ++c) {
            const uint4* gB = g_w0B + (c * 32 + lid) * 4;
            uint4 B0 = gB[0], B1 = gB[1], B2 = gB[2], B3 = gB[3];
#pragma unroll
            for (int u = 0; u < 4; ++u) {
                uint32_t ha0 = sHi[rb[u][0] + off0[c]], ha1 = sHi[rb[u][1] + off0[c]];
                uint32_t ha2 = sHi[rb[u][0] + off2[c]], ha3 = sHi[rb[u][1] + off2[c]];
                uint32_t la0 = sLo[rb[u][0] + off0[c]], la1 = sLo[rb[u][1] + off0[c]];
                uint32_t la2 = sLo[rb[u][0] + off2[c]], la3 = sLo[rb[u][1] + off2[c]];
                mma_bf16(acc[u][0], ha0, ha1, ha2, ha3, B0.x, B0.y);
                mma_bf16(acc[u][1], ha0, ha1, ha2, ha3, B1.x, B1.y);
                mma_bf16(acc[u][2], ha0, ha1, ha2, ha3, B2.x, B2.y);
                mma_bf16(acc[u][3], ha0, ha1, ha2, ha3, B3.x, B3.y);
                mma_bf16(acc[u][0], la0, la1, la2, la3, B0.x, B0.y);
                mma_bf16(acc[u][1], la0, la1, la2, la3, B1.x, B1.y);
                mma_bf16(acc[u][2], la0, la1, la2, la3, B2.x, B2.y);
                mma_bf16(acc[u][3], la0, la1, la2, la3, B3.x, B3.y);
                mma_bf16(acc[u][0], ha0, ha1, ha2, ha3, B0.z, B0.w);
                mma_bf16(acc[u][1], ha0, ha1, ha2, ha3, B1.z, B1.w);
                mma_bf16(acc[u][2], ha0, ha1, ha2, ha3, B2.z, B2.w);
                mma_bf16(acc[u][3], ha0, ha1, ha2, ha3, B3.z, B3.w);
            }
        }
#pragma unroll
        for (int u = 0; u < 4; ++u) {
            const int tt = wid * 16 + tq * 4 + u;
            const int qA = tt * 4 + qoff;
            const int qB = qA + 2;
#pragma unroll
            for (int nf = 0; nf < 4; ++nf) {
                float vx = prelu(acc[u][nf].x + bx[nf], a);
                float vy = prelu(acc[u][nf].y + by[nf], a);
                float vz = prelu(acc[u][nf].z + bx[nf], a);
                float vw = prelu(acc[u][nf].w + by[nf], a);
                vx = fmaxf(vx, __shfl_xor_sync(0xffffffffu, vx, 4));
                vx = fmaxf(vx, __shfl_xor_sync(0xffffffffu, vx, 8));
                vy = fmaxf(vy, __shfl_xor_sync(0xffffffffu, vy, 4));
                vy = fmaxf(vy, __shfl_xor_sync(0xffffffffu, vy, 8));
                vz = fmaxf(vz, __shfl_xor_sync(0xffffffffu, vz, 4));
                vz = fmaxf(vz, __shfl_xor_sync(0xffffffffu, vz, 8));
                vw = fmaxf(vw, __shfl_xor_sync(0xffffffffu, vw, 4));
                vw = fmaxf(vw, __shfl_xor_sync(0xffffffffu, vw, 8));
                if (wr) {
                    int oc0 = nf * 8 + 2 * cb;
                    if (qA < 441) {
                        out[oc0 * 441 + qA]       = vx;
                        out[(oc0 + 1) * 441 + qA] = vy;
                    }
                    if (qB < 441) {
                        out[oc0 * 441 + qB]       = vz;
                        out[(oc0 + 1) * 441 + qB] = vw;
                    }
                }
            }
        }
    }
}

// conv1 (R14 interleaved uint2, stride 20)
#define C1_STR  20
#define C1_U2   (484 * C1_STR)
#define SMEM_C1 (C1_U2 * 8)

__global__ void __launch_bounds__(224, 2)
k_conv1_mma(const float* __restrict__ b, const float* __restrict__ ap) {
    extern __shared__ uint2 sI1[];
    const int tid = threadIdx.x, wid = tid >> 5, lid = tid & 31, bl = blockIdx.x;

    for (int i = tid; i < C1_U2; i += 224) sI1[i] = make_uint2(0u, 0u);
    __syncthreads();
    const float* src = g_s0 + bl * 14112;
    for (int i = tid; i < 7056; i += 224) {
        int pr = i / 441, pix = i - pr * 441;
        int y = pix / 21, x = pix - y * 21;
        float v0 = src[(2 * pr) * 441 + pix];
        float v1 = src[(2 * pr + 1) * 441 + pix];
        uint32_t hp, lp;
        split2(v0, v1, hp, lp);
        sI1[((y + 1) * 22 + (x + 1)) * C1_STR + pr] = make_uint2(hp, lp);
    }
    __syncthreads();

    int base[3][2];
#pragma unroll
    for (int t = 0; t < 3; ++t)
#pragma unroll
        for (int j = 0; j < 2; ++j) {
            int m = (wid * 3 + t) * 16 + (lid >> 2) + j * 8;
            int mm = m < 324 ? m : 0;
            int ym = mm / 18, xm = mm - ym * 18;
            base[t][j] = (ym * 22 + xm) * C1_STR;
        }

    float4 acc[3][4];
#pragma unroll
    for (int t = 0; t < 3; ++t)
#pragma unroll
        for (int nf = 0; nf < 4; ++nf) acc[t][nf] = make_float4(0.f, 0.f, 0.f, 0.f);

    const int cb = lid & 3;
    for (int p = 0; p < 25; ++p) {
        const int ky = p / 5, kx = p - ky * 5;
        const int off = (ky * 22 + kx) * C1_STR;
#pragma unroll
        for (int g = 0; g < 2; ++g) {
            const uint4* gB = g_w1B + ((p * 2 + g) * 32 + lid) * 4;
            uint4 B0 = gB[0], B1 = gB[1], B2 = gB[2], B3 = gB[3];
            const int c = g * 8 + cb;
#pragma unroll
            for (int t = 0; t < 3; ++t) {
                const int i0 = base[t][0] + off + c;
                const int i1 = base[t][1] + off + c;
                uint2 A0 = sI1[i0];
                uint2 A1 = sI1[i1];
                uint2 A2 = sI1[i0 + 4];
                uint2 A3 = sI1[i1 + 4];
                mma_bf16(acc[t][0], A0.x, A1.x, A2.x, A3.x, B0.x, B0.y);
                mma_bf16(acc[t][1], A0.x, A1.x, A2.x, A3.x, B1.x, B1.y);
                mma_bf16(acc[t][2], A0.x, A1.x, A2.x, A3.x, B2.x, B2.y);
                mma_bf16(acc[t][3], A0.x, A1.x, A2.x, A3.x, B3.x, B3.y);
                mma_bf16(acc[t][0], A0.y, A1.y, A2.y, A3.y, B0.x, B0.y);
                mma_bf16(acc[t][1], A0.y, A1.y, A2.y, A3.y, B1.x, B1.y);
                mma_bf16(acc[t][2], A0.y, A1.y, A2.y, A3.y, B2.x, B2.y);
                mma_bf16(acc[t][3], A0.y, A1.y, A2.y, A3.y, B3.x, B3.y);
                mma_bf16(acc[t][0], A0.x, A1.x, A2.x, A3.x, B0.z, B0.w);
                mma_bf16(acc[t][1], A0.x, A1.x, A2.x, A3.x, B1.z, B1.w);
                mma_bf16(acc[t][2], A0.x, A1.x, A2.x, A3.x, B2.z, B2.w);
                mma_bf16(acc[t][3], A0.x, A1.x, A2.x, A3.x, B3.z, B3.w);
            }
        }
    }
    __syncthreads();

    const float a = *ap;
    float* stage = (float*)sI1;
    {
        const int r0 = (wid * 3) * 16 + (lid >> 2);
        const int oc0 = 2 * (lid & 3);
#pragma unroll
        for (int t = 0; t < 3; ++t) {
            int ra = r0 + t * 16, rb2 = ra + 8;
#pragma unroll
            for (int nf = 0; nf < 4; ++nf) {
                int ca = nf * 8 + oc0;
                float ba = b[ca], bb = b[ca + 1];
                stage[ra * 33 + ca]      = prelu(acc[t][nf].x + ba, a);
                stage[ra * 33 + ca + 1]  = prelu(acc[t][nf].y + bb, a);
                stage[rb2 * 33 + ca]     = prelu(acc[t][nf].z + ba, a);
                stage[rb2 * 33 + ca + 1] = prelu(acc[t][nf].w + bb, a);
            }
        }
    }
    __syncthreads();

    float* outp = g_s1 + bl * 2592;
    for (int i = tid; i < 2592; i += 224) {
        int oc = i / 81, pp = i - oc * 81;
        int py = pp / 9, px = pp - py * 9;
        int m00 = (2 * py) * 18 + 2 * px;
        float v = fmaxf(fmaxf(stage[m00 * 33 + oc],        stage[(m00 + 1) * 33 + oc]),
                        fmaxf(stage[(m00 + 18) * 33 + oc], stage[(m00 + 19) * 33 + oc]));
        outp[i] = v;
    }
}

// conv2 (R14 interleaved uint2)
#define C2_STR  20
#define C2_IMGU (121 * C2_STR)
#define SMEM_C2 (2 * C2_IMGU * 8)

__global__ void __launch_bounds__(256, 2)
k_conv2_mma(const float* __restrict__ b, const float* __restrict__ ap) {
    extern __shared__ uint2 sI2[];
    const int tid = threadIdx.x, wid = tid >> 5, lid = tid & 31, bl = blockIdx.x;

    for (int i = tid; i < 2 * C2_IMGU; i += 256) sI2[i] = make_uint2(0u, 0u);
    __syncthreads();
    const float* src = g_s1 + bl * 2 * 2592;
    for (int i = tid; i < 2592; i += 256) {
        int img = i / 1296, rr = i - img * 1296;
        int pr = rr / 81, pix = rr - pr * 81;
        int y = pix / 9, x = pix - y * 9;
        float v0 = src[img * 2592 + (2 * pr) * 81 + pix];
        float v1 = src[img * 2592 + (2 * pr + 1) * 81 + pix];
        uint32_t hp, lp;
        split2(v0, v1, hp, lp);
        sI2[img * C2_IMGU + ((y + 1) * 11 + (x + 1)) * C2_STR + pr] = make_uint2(hp, lp);
    }
    __syncthreads();

    const int img = wid >> 2;
    int base[2];
#pragma unroll
    for (int j = 0; j < 2; ++j) {
        int m = wid * 16 + (lid >> 2) + j * 8;
        int pix = m & 63;
        int oy = pix >> 3, ox = pix & 7;
        base[j] = img * C2_IMGU + (oy * 11 + ox) * C2_STR;
    }

    float4 acc[8];
#pragma unroll
    for (int nf = 0; nf < 8; ++nf) acc[nf] = make_float4(0.f, 0.f, 0.f, 0.f);

    const int cb = lid & 3;
    for (int p = 0; p < 16; ++p) {
        const int off = ((p >> 2) * 11 + (p & 3)) * C2_STR;
#pragma unroll
        for (int g = 0; g < 2; ++g) {
            const uint4* gB = g_w2B + ((p * 2 + g) * 32 + lid) * 8;
            const int c = g * 8 + cb;
            const int i0 = base[0] + off + c;
            const int i1 = base[1] + off + c;
            uint2 A0 = sI2[i0];
            uint2 A1 = sI2[i1];
            uint2 A2 = sI2[i0 + 4];
            uint2 A3 = sI2[i1 + 4];
#pragma unroll
            for (int nf = 0; nf < 8; ++nf) {
                uint4 Bv = gB[nf];
                mma_bf16(acc[nf], A0.x, A1.x, A2.x, A3.x, Bv.x, Bv.y);
                mma_bf16(acc[nf], A0.y, A1.y, A2.y, A3.y, Bv.x, Bv.y);
                mma_bf16(acc[nf], A0.x, A1.x, A2.x, A3.x, Bv.z, Bv.w);
            }
        }
    }
    __syncthreads();

    const float a = *ap;
    float* stage = (float*)sI2;
    {
        const int r0 = wid * 16 + (lid >> 2);
        const int oc0 = 2 * (lid & 3);
#pragma unroll
        for (int nf = 0; nf < 8; ++nf) {
            int ca = nf * 8 + oc0;
            float ba = b[ca], bb = b[ca + 1];
            stage[r0 * 65 + ca]           = prelu(acc[nf].x + ba, a);
            stage[r0 * 65 + ca + 1]       = prelu(acc[nf].y + bb, a);
            stage[(r0 + 8) * 65 + ca]     = prelu(acc[nf].z + ba, a);
            stage[(r0 + 8) * 65 + ca + 1] = prelu(acc[nf].w + bb, a);
        }
    }
    __syncthreads();

    for (int i = tid; i < 2048; i += 256) {
        int im = i >> 10, rem = i & 1023;
        int oc = rem >> 4, pp = rem & 15;
        int py = pp >> 2, px = pp & 3;
        int m00 = im * 64 + (2 * py) * 8 + 2 * px;
        float v = fmaxf(fmaxf(stage[m00 * 65 + oc],       stage[(m00 + 1) * 65 + oc]),
                        fmaxf(stage[(m00 + 8) * 65 + oc], stage[(m00 + 9) * 65 + oc]));
        g_s2[((bl * 2 + im) * 64 + oc) * 16 + py * 4 + px] = v;
    }
}

// conv3 (R15 chunked weights, 3 CTAs/SM)
#define C3_WCH (64 * 145)
#define SMEM_C3 ((C3_WCH + 8192) * 4)

__global__ void __launch_bounds__(256, 3)
k_conv3(const float* __restrict__ w,
        const float* __restrict__ b,
        const float* __restrict__ ap) {
    extern __shared__ float sm3[];
    float* sW  = sm3;
    float* sIn = sm3 + C3_WCH;
    const int tid = threadIdx.x;
    const int bl0 = blockIdx.x * 8;

    const float* src = g_s2 + bl0 * 1024;
    for (int i = tid; i < 8192; i += 256) sIn[i] = src[i];

    const int oc = tid >> 2, pos = tid & 3;
    const int yy = pos >> 1, xx = pos & 1;
    const float bias = b[oc];
    const float a = *ap;

    float acc[8];
#pragma unroll
    for (int i = 0; i < 8; ++i) acc[i] = bias;

    for (int ch = 0; ch < 4; ++ch) {
        __syncthreads();
        for (int k = tid; k < 64 * 144; k += 256) {
            int o = k / 144, r = k - o * 144;
            sW[o * 145 + r] = w[o * 576 + ch * 144 + r];
        }
        __syncthreads();
#pragma unroll
        for (int icl = 0; icl < 16; ++icl) {
            const int ic = ch * 16 + icl;
            const float* wv = sW + oc * 145 + icl * 9;
            float wr[9];
#pragma unroll
            for (int j = 0; j < 9; ++j) wr[j] = wv[j];
#pragma unroll
            for (int img = 0; img < 8; ++img) {
                const float* ip = sIn + img * 1024 + ic * 16;
#pragma unroll
                for (int ky = 0; ky < 3; ++ky)
#pragma unroll
                    for (int kx = 0; kx < 3; ++kx)
                        acc[img] = fmaf(ip[(yy + ky) * 4 + (xx + kx)], wr[ky * 3 + kx], acc[img]);
            }
        }
    }
#pragma unroll
    for (int img = 0; img < 8; ++img)
        g_s3[(bl0 + img) * 256 + oc * 4 + pos] = prelu(acc[img], a);
}

// FC heads (per-image)
__global__ void k_fc(const float* __restrict__ fc1_w, const float* __restrict__ fc1_b,
                     const float* __restrict__ a4,
                     const float* __restrict__ fc2_w, const float* __restrict__ fc2_b,
                     const float* __restrict__ a5,
                     const float* __restrict__ fc3_w, const float* __restrict__ fc3_b,
                     float* __restrict__ out) {
    __shared__ float feat[256];
    __shared__ float h1[128];
    __shared__ float h2[64];
    const int bl = blockIdx.x, l = bl % 6, tid = threadIdx.x;

    feat[tid]       = g_s3[bl * 256 + tid];
    feat[tid + 128] = g_s3[bl * 256 + 128 + tid];
    __syncthreads();
    {
        float acc = fc1_b[l * 128 + tid];
        const float* W = fc1_w + l * 256 * 128 + tid;
#pragma unroll 8
        for (int i = 0; i < 256; ++i) acc = fmaf(feat[i], W[i * 128], acc);
        h1[tid] = prelu(acc, a4[l]);
    }
    __syncthreads();
    if (tid < 64) {
        float acc = fc2_b[l * 64 + tid];
        const float* W = fc2_w + l * 128 * 64 + tid;
#pragma unroll 8
        for (int i = 0; i < 128; ++i) acc = fmaf(h1[i], W[i * 64], acc);
        h2[tid] = prelu(acc, a5[l]);
    }
    __syncthreads();
    if (tid < 4) {
        float acc = fc3_b[l * 4 + tid];
        const float* W = fc3_w + l * 64 * 4 + tid;
#pragma unroll
        for (int i = 0; i < 64; ++i) acc = fmaf(h2[i], W[i * 4], acc);
        out[bl * 4 + tid] = acc;
    }
}

extern "C" void kernel_launch(void* const* d_in, const int* in_sizes, int n_in,
                              void* d_out, int out_size) {
    const float* x     = (const float*)d_in[0];
    const float* w0    = (const float*)d_in[1];
    const float* b0    = (const float*)d_in[2];
    const float* w1    = (const float*)d_in[3];
    const float* b1    = (const float*)d_in[4];
    const float* w2    = (const float*)d_in[5];
    const float* b2    = (const float*)d_in[6];
    const float* w3    = (const float*)d_in[7];
    const float* b3    = (const float*)d_in[8];
    const float* a0    = (const float*)d_in[9];
    const float* a1    = (const float*)d_in[10];
    const float* a2    = (const float*)d_in[11];
    const float* a3    = (const float*)d_in[12];
    const float* fc1_w = (const float*)d_in[13];
    const float* fc1_b = (const float*)d_in[14];
    const float* a4    = (const float*)d_in[15];
    const float* fc2_w = (const float*)d_in[16];
    const float* fc2_b = (const float*)d_in[17];
    const float* a5    = (const float*)d_in[18];
    const float* fc3_w = (const float*)d_in[19];
    const float* fc3_b = (const float*)d_in[20];
    float* out = (float*)d_out;

    cudaFuncSetAttribute(k_conv0_mma, cudaFuncAttributeMaxDynamicSharedMemorySize, SMEM_C0);
    cudaFuncSetAttribute(k_conv1_mma, cudaFuncAttributeMaxDynamicSharedMemorySize, SMEM_C1);
    cudaFuncSetAttribute(k_conv2_mma, cudaFuncAttributeMaxDynamicSharedMemorySize, SMEM_C2);
    cudaFuncSetAttribute(k_conv3, cudaFuncAttributeMaxDynamicSharedMemorySize, SMEM_C3);

    k_w0prep<<<7, 128>>>(w0);
    k_w1prep<<<dim3(25, 2), 128>>>(w1);
    k_w2prep<<<dim3(16, 2), 256>>>(w2);
    k_conv0_mma<<<BL, 224, SMEM_C0>>>(x, b0, a0);
    k_conv1_mma<<<BL, 224, SMEM_C1>>>(b1, a1);
    k_conv2_mma<<<BL / 2, 256, SMEM_C2>>>(b2, a2);
    k_conv3<<<BL / 8, 256, SMEM_C3>>>(w3, b3, a3);
    k_fc<<<BL, 128>>>(fc1_w, fc1_b, a4, fc2_w, fc2_b, a5, fc3_w, fc3_b, out);
}